// round 6
// baseline (speedup 1.0000x reference)
#include <cuda_runtime.h>
#include <cuda_fp16.h>
#include <cstdint>
#include <cstddef>

#define DEVINL __device__ __forceinline__

constexpr int MROWS = 16384;
constexpr int KTOT  = 1024;
constexpr int NCOLS = 1024;

// GEMM tiling: CTA 64x128, warp tile 32x64 (4 warps: 2 over M, 2 over N), 3 CTAs/SM
constexpr int BM = 64, BN = 128, BK = 64;       // BK in fp16 elements (128B row)
constexpr int STAGES = 3;
constexpr int TPB = 128;
constexpr int NCHUNK = KTOT / BK;               // 16

constexpr int A_BYTES = BM * BK * 2;            // 8 KB
constexpr int B_BYTES = BN * BK * 2;            // 16 KB
constexpr int STAGE_BYTES = A_BYTES + B_BYTES;  // 24 KB
constexpr int SMEM_TOTAL = STAGES * STAGE_BYTES; // 72 KB (x3 CTAs = 216 KB/SM)

// Static device scratch (allocation-free rule)
__device__ __half g_ah[(size_t)MROWS * KTOT];   // A converted to fp16
__device__ __half g_wt[(size_t)NCOLS * KTOT];   // W quantized, [n][k] K-major

// prep kernel split point
constexpr int CONV_BLOCKS  = 4096;   // 4096 blk * 256 thr * 4 float4 = 4.19M float4
constexpr int QUANT_BLOCKS = (NCOLS / 32) * (KTOT / 32);  // 1024
constexpr int CONV_STRIDE  = CONV_BLOCKS * 256;           // float4 elements

// ---------------------------------------------------------------- helpers
DEVINL uint32_t smem_u32(const void* p) {
    uint32_t r;
    asm("{ .reg .u64 t; cvta.to.shared.u64 t, %1; cvt.u32.u64 %0, t; }"
        : "=r"(r) : "l"(p));
    return r;
}
DEVINL uint32_t swz(uint32_t off) {            // SW128: bits[6:4] ^= bits[9:7]
    return off ^ ((off >> 3) & 0x70);
}
DEVINL void cp_async16(uint32_t s, const void* g) {
    asm volatile("cp.async.cg.shared.global [%0], [%1], 16;"
                 :: "r"(s), "l"(g) : "memory");
}
DEVINL void cp_commit() {
    asm volatile("cp.async.commit_group;" ::: "memory");
}
template <int N> DEVINL void cp_wait() {
    asm volatile("cp.async.wait_group %0;" :: "n"(N) : "memory");
}
DEVINL void ldsm_x4(uint32_t* r, uint32_t addr) {
    asm volatile("ldmatrix.sync.aligned.m8n8.x4.shared.b16 {%0,%1,%2,%3}, [%4];"
                 : "=r"(r[0]), "=r"(r[1]), "=r"(r[2]), "=r"(r[3]) : "r"(addr));
}
DEVINL void mma16816(float* c, const uint32_t* a, const uint32_t* b) {
    asm volatile(
        "mma.sync.aligned.m16n8k16.row.col.f32.f16.f16.f32 "
        "{%0,%1,%2,%3}, {%4,%5,%6,%7}, {%8,%9}, {%0,%1,%2,%3};"
        : "+f"(c[0]), "+f"(c[1]), "+f"(c[2]), "+f"(c[3])
        : "r"(a[0]), "r"(a[1]), "r"(a[2]), "r"(a[3]), "r"(b[0]), "r"(b[1]));
}
DEVINL uint32_t pack_half2(float x, float y) {
    __half2 h = __floats2half2_rn(x, y);
    return *reinterpret_cast<uint32_t*>(&h);
}

// -------------------------------------------- merged prep kernel
// blocks [0, CONV_BLOCKS):             A fp32 -> fp16 (4 float4 per thread, MLP=4)
// blocks [CONV_BLOCKS, +QUANT_BLOCKS): W quantize + transpose
__global__ void prep_kernel(const float4* __restrict__ a,
                            const float* __restrict__ w) {
    const int bid = blockIdx.x;
    const int t   = threadIdx.x;

    if (bid < CONV_BLOCKS) {
        const size_t base = (size_t)bid * 256 + t;
        float4 v0 = a[base];
        float4 v1 = a[base + CONV_STRIDE];
        float4 v2 = a[base + 2 * (size_t)CONV_STRIDE];
        float4 v3 = a[base + 3 * (size_t)CONV_STRIDE];
        uint2 o0 = make_uint2(pack_half2(v0.x, v0.y), pack_half2(v0.z, v0.w));
        uint2 o1 = make_uint2(pack_half2(v1.x, v1.y), pack_half2(v1.z, v1.w));
        uint2 o2 = make_uint2(pack_half2(v2.x, v2.y), pack_half2(v2.z, v2.w));
        uint2 o3 = make_uint2(pack_half2(v3.x, v3.y), pack_half2(v3.z, v3.w));
        uint2* out = reinterpret_cast<uint2*>(g_ah);
        out[base]                           = o0;
        out[base + CONV_STRIDE]             = o1;
        out[base + 2 * (size_t)CONV_STRIDE] = o2;
        out[base + 3 * (size_t)CONV_STRIDE] = o3;
    } else {
        __shared__ __half tile[32][33];
        const int tb = bid - CONV_BLOCKS;
        const int n0 = (tb & 31) * 32;
        const int k0 = (tb >> 5) * 32;
        const int tx = t & 31;
        const int ty = t >> 5;
        #pragma unroll
        for (int i = ty; i < 32; i += 8) {
            float x = w[(size_t)(k0 + i) * NCOLS + n0 + tx];
            x = fminf(fmaxf(x, -0.5f), 0.5f);     // clip [-1+delta, 1-delta]
            float y = rintf(x * 2.0f) * 0.5f;     // round-half-even, step 0.5
            tile[i][tx] = __float2half_rn(y);     // exact in fp16
        }
        __syncthreads();
        #pragma unroll
        for (int i = ty; i < 32; i += 8) {
            g_wt[(size_t)(n0 + i) * KTOT + k0 + tx] = tile[tx][i];
        }
    }
}

// ------------------------------------------------------------- main GEMM
__global__ void __launch_bounds__(TPB, 3)
gemm_hmma_kernel(float* __restrict__ C) {
    extern __shared__ char smem[];
    const uint32_t sb = smem_u32(smem);
    const int tid  = threadIdx.x;
    const int lane = tid & 31;
    const int wid  = tid >> 5;
    const int warpM = wid & 1;    // 2 warps over M -> 32 rows each
    const int warpN = wid >> 1;   // 2 warps over N -> 64 cols each

    const int m0 = blockIdx.y * BM;
    const int n0 = blockIdx.x * BN;

    const char* aG = (const char*)(g_ah + (size_t)m0 * KTOT);
    const char* bG = (const char*)(g_wt + (size_t)n0 * KTOT);

    // per-thread cp.async mapping: 16 rows x 8 chunks of 16B per pass
    const int lr = tid >> 3;             // row 0..15
    const int lc = (tid & 7) * 16;       // byte offset within 128B row
    const uint32_t ld_sw0 = swz(lr * 128 + lc);   // +2048B steps keep XOR mask

    auto load_stage = [&](int kc, int s) {
        const uint32_t aS = sb + s * STAGE_BYTES;
        const uint32_t bS = aS + A_BYTES;
        const char* ag = aG + (size_t)lr * (KTOT * 2) + kc * (BK * 2) + lc;
        const char* bg = bG + (size_t)lr * (KTOT * 2) + kc * (BK * 2) + lc;
        #pragma unroll
        for (int it = 0; it < 4; it++) {           // A: 64 rows
            cp_async16(aS + ld_sw0 + it * 2048,
                       ag + (size_t)it * 16 * KTOT * 2);
        }
        #pragma unroll
        for (int it = 0; it < 8; it++) {           // B: 128 rows
            cp_async16(bS + ld_sw0 + it * 2048,
                       bg + (size_t)it * 16 * KTOT * 2);
        }
    };

    // hoisted ldmatrix address bases (offset within stage, ki=0)
    uint32_t aBase[2], bBase[4];
    #pragma unroll
    for (int mi = 0; mi < 2; mi++) {
        const int row = warpM * 32 + mi * 16 + (lane & 15);
        const int ko  = (lane >> 4) * 8;
        aBase[mi] = swz(row * 128 + ko * 2);
    }
    #pragma unroll
    for (int nj = 0; nj < 4; nj++) {
        const int row = warpN * 64 + nj * 16 + ((lane >> 4) << 3) + (lane & 7);
        const int ko  = ((lane >> 3) & 1) * 8;
        bBase[nj] = swz(row * 128 + ko * 2) + A_BYTES;
    }

    // prologue: stages 0..STAGES-2
    #pragma unroll
    for (int s = 0; s < STAGES - 1; s++) {
        load_stage(s, s);
        cp_commit();
    }

    float acc[2][8][4] = {};
    uint32_t afr[2][2][4], bfr[2][4][4];   // ping-pong fragment buffers

    for (int kc = 0; kc < NCHUNK; kc++) {
        // R4-proven ordering: per-thread wait, then CTA-wide publish barrier.
        cp_wait<STAGES - 2>();   // this thread's stage-kc copies done
        __syncthreads();         // ALL threads' copies visible; slot (kc+2)%3
                                 // is also reusable (kc-1 compute finished)

        if (kc + STAGES - 1 < NCHUNK)
            load_stage(kc + STAGES - 1, (kc + STAGES - 1) % STAGES);
        cp_commit();             // unconditional: keeps group indices uniform

        const uint32_t stS = sb + (kc % STAGES) * STAGE_BYTES;

        // prime fragments for ki=0
        #pragma unroll
        for (int mi = 0; mi < 2; mi++) ldsm_x4(afr[0][mi], stS + aBase[mi]);
        #pragma unroll
        for (int nj = 0; nj < 4; nj++) ldsm_x4(bfr[0][nj], stS + bBase[nj]);

        #pragma unroll
        for (int ki = 0; ki < BK / 16; ki++) {       // 4 k16 steps
            const int cur = ki & 1, nxt = cur ^ 1;
            if (ki < BK / 16 - 1) {                  // prefetch ki+1 fragments
                const uint32_t kOff = (ki + 1) * 32; // 32B steps are XOR-safe
                #pragma unroll
                for (int mi = 0; mi < 2; mi++)
                    ldsm_x4(afr[nxt][mi], stS + (aBase[mi] ^ kOff));
                #pragma unroll
                for (int nj = 0; nj < 4; nj++)
                    ldsm_x4(bfr[nxt][nj], stS + (bBase[nj] ^ kOff));
            }
            #pragma unroll
            for (int mi = 0; mi < 2; mi++)
                #pragma unroll
                for (int nj = 0; nj < 8; nj++)
                    mma16816(acc[mi][nj], afr[cur][mi],
                             &bfr[cur][nj >> 1][(nj & 1) * 2]);
        }
    }

    // ---- epilogue: direct coalesced-by-quad float2 stores
    float* cBase = C + (size_t)(m0 + warpM * 32) * NCOLS + n0 + warpN * 64;
    const int cr = lane >> 2;
    const int cc = (lane & 3) * 2;
    #pragma unroll
    for (int mi = 0; mi < 2; mi++) {
        #pragma unroll
        for (int nj = 0; nj < 8; nj++) {
            float* p0 = cBase + (size_t)(mi * 16 + cr) * NCOLS + nj * 8 + cc;
            float* p1 = p0 + 8 * NCOLS;
            *reinterpret_cast<float2*>(p0) = make_float2(acc[mi][nj][0], acc[mi][nj][1]);
            *reinterpret_cast<float2*>(p1) = make_float2(acc[mi][nj][2], acc[mi][nj][3]);
        }
    }
}

// ---------------------------------------------------------------- launch
extern "C" void kernel_launch(void* const* d_in, const int* in_sizes, int n_in,
                              void* d_out, int out_size) {
    (void)in_sizes; (void)n_in; (void)out_size;
    const float* A = (const float*)d_in[0];   // [16384, 1024] fp32
    const float* W = (const float*)d_in[1];   // [1024, 1024] fp32
    float* C = (float*)d_out;                 // [16384, 1024] fp32

    prep_kernel<<<CONV_BLOCKS + QUANT_BLOCKS, 256>>>(
        reinterpret_cast<const float4*>(A), W);

    cudaFuncSetAttribute(gemm_hmma_kernel,
                         cudaFuncAttributeMaxDynamicSharedMemorySize, SMEM_TOTAL);
    gemm_hmma_kernel<<<dim3(NCOLS / BN, MROWS / BM), TPB, SMEM_TOTAL>>>(C);
}

// round 7
// speedup vs baseline: 1.3679x; 1.3679x over previous
#include <cuda_runtime.h>
#include <cuda_fp16.h>
#include <cstdint>
#include <cstddef>

#define DEVINL __device__ __forceinline__

constexpr int MROWS = 16384;
constexpr int KTOT  = 1024;
constexpr int NCOLS = 1024;

// GEMM tiling: CTA 128x128, warp tile 32x64 (8 warps: 4 over M, 2 over N), 2 CTAs/SM
constexpr int BM = 128, BN = 128, BK = 64;
constexpr int STAGES = 3;
constexpr int TPB = 256;
constexpr int NCHUNK = KTOT / BK;               // 16

constexpr int A_BYTES = BM * BK * 2;            // 16 KB (fp16, SW128)
constexpr int P_BYTES = 8 * 1024;               // 8 KB packed-B selectors
constexpr int STAGE_BYTES = A_BYTES + P_BYTES;  // 24 KB
constexpr int SMEM_TOTAL = STAGES * STAGE_BYTES; // 72 KB (x2 CTAs = 144 KB/SM)

// Static device scratch (allocation-free rule)
__device__ __half g_ah[(size_t)MROWS * KTOT];   // A converted to fp16
// Packed B selectors: [Jblk(8)][I(64)][Jp(8)][lane(32)][e(2)] u32  (1 MB)
// J = n/8 (n8-tile), I = k/16 (k16-tile), Jblk=J>>4, Jp=(J>>1)&7, e=J&1.
// Word w = s0 | (s1<<16); s = 0x0101 | (c_lo<<4) | (c_hi<<12);
// code c = rint(2*clip(x)) + 1  in {0,1,2}  ->  LUT byte {0xB8, 0x00, 0x38}.
__device__ uint32_t g_wp[8 * 64 * 8 * 32 * 2];

constexpr uint32_t PRMT_LUT = 0x003800B8u;      // idx0=0xB8(-0.5h) idx1=0x00 idx2=0x38(+0.5h)

// prep split
constexpr int CONV_BLOCKS = 4096;   // A convert: 4 float4 per thread
constexpr int PACK_BLOCKS = 1024;   // 1024 blk * 8 warps = 8192 = 128 J * 64 I
constexpr int CONV_STRIDE = CONV_BLOCKS * 256;

// ---------------------------------------------------------------- helpers
DEVINL uint32_t smem_u32(const void* p) {
    uint32_t r;
    asm("{ .reg .u64 t; cvta.to.shared.u64 t, %1; cvt.u32.u64 %0, t; }"
        : "=r"(r) : "l"(p));
    return r;
}
DEVINL uint32_t swz(uint32_t off) { return off ^ ((off >> 3) & 0x70); }
DEVINL void cp_async16(uint32_t s, const void* g) {
    asm volatile("cp.async.cg.shared.global [%0], [%1], 16;"
                 :: "r"(s), "l"(g) : "memory");
}
DEVINL void cp_commit() { asm volatile("cp.async.commit_group;" ::: "memory"); }
template <int N> DEVINL void cp_wait() {
    asm volatile("cp.async.wait_group %0;" :: "n"(N) : "memory");
}
DEVINL void ldsm_x4(uint32_t* r, uint32_t addr) {
    asm volatile("ldmatrix.sync.aligned.m8n8.x4.shared.b16 {%0,%1,%2,%3}, [%4];"
                 : "=r"(r[0]), "=r"(r[1]), "=r"(r[2]), "=r"(r[3]) : "r"(addr));
}
DEVINL void lds_v2(uint32_t& w0, uint32_t& w1, uint32_t addr) {
    asm volatile("ld.shared.v2.u32 {%0, %1}, [%2];"
                 : "=r"(w0), "=r"(w1) : "r"(addr));
}
DEVINL uint32_t prmt(uint32_t sel) {
    uint32_t d;
    asm("prmt.b32 %0, %1, 0, %2;" : "=r"(d) : "r"(PRMT_LUT), "r"(sel));
    return d;
}
DEVINL void mma16816(float* c, const uint32_t* a, const uint32_t* b) {
    asm volatile(
        "mma.sync.aligned.m16n8k16.row.col.f32.f16.f16.f32 "
        "{%0,%1,%2,%3}, {%4,%5,%6,%7}, {%8,%9}, {%0,%1,%2,%3};"
        : "+f"(c[0]), "+f"(c[1]), "+f"(c[2]), "+f"(c[3])
        : "r"(a[0]), "r"(a[1]), "r"(a[2]), "r"(a[3]), "r"(b[0]), "r"(b[1]));
}
DEVINL uint32_t pack_half2(float x, float y) {
    __half2 h = __floats2half2_rn(x, y);
    return *reinterpret_cast<uint32_t*>(&h);
}
DEVINL uint32_t wcode(float x) {       // quantize -> selector code {0,1,2}
    x = fminf(fmaxf(x, -0.5f), 0.5f);
    return (uint32_t)(int)(rintf(x * 2.0f) + 1.0f);
}

// -------------------------------------------- merged prep kernel
__global__ void prep_kernel(const float4* __restrict__ a,
                            const float* __restrict__ w) {
    const int bid = blockIdx.x;
    const int t   = threadIdx.x;

    if (bid < CONV_BLOCKS) {           // A fp32 -> fp16, MLP=4
        const size_t base = (size_t)bid * 256 + t;
        float4 v0 = a[base];
        float4 v1 = a[base + CONV_STRIDE];
        float4 v2 = a[base + 2 * (size_t)CONV_STRIDE];
        float4 v3 = a[base + 3 * (size_t)CONV_STRIDE];
        uint2* out = reinterpret_cast<uint2*>(g_ah);
        out[base]                           = make_uint2(pack_half2(v0.x, v0.y), pack_half2(v0.z, v0.w));
        out[base + CONV_STRIDE]             = make_uint2(pack_half2(v1.x, v1.y), pack_half2(v1.z, v1.w));
        out[base + 2 * (size_t)CONV_STRIDE] = make_uint2(pack_half2(v2.x, v2.y), pack_half2(v2.z, v2.w));
        out[base + 3 * (size_t)CONV_STRIDE] = make_uint2(pack_half2(v3.x, v3.y), pack_half2(v3.z, v3.w));
    } else {                           // W quantize + pack selectors
        const int g    = (bid - CONV_BLOCKS) * 8 + (t >> 5);  // 0..8191
        const int lane = t & 31;
        const int J = g >> 6;          // n8-tile 0..127
        const int I = g & 63;          // k16-tile 0..63
        const int n  = J * 8 + (lane >> 2);
        const int kb = I * 16 + (lane & 3) * 2;
        const uint32_t c0 = wcode(w[(size_t)kb * NCOLS + n]);
        const uint32_t c1 = wcode(w[(size_t)(kb + 1) * NCOLS + n]);
        const uint32_t c2 = wcode(w[(size_t)(kb + 8) * NCOLS + n]);
        const uint32_t c3 = wcode(w[(size_t)(kb + 9) * NCOLS + n]);
        const uint32_t s0 = 0x0101u | (c0 << 4) | (c1 << 12);
        const uint32_t s1 = 0x0101u | (c2 << 4) | (c3 << 12);
        const int Jblk = J >> 4, Jp = (J >> 1) & 7, e = J & 1;
        g_wp[(((size_t)(Jblk * 64 + I) * 8 + Jp) * 32 + lane) * 2 + e] = s0 | (s1 << 16);
    }
}

// ------------------------------------------------------------- main GEMM
__global__ void __launch_bounds__(TPB, 2)
gemm_hmma_kernel(float* __restrict__ C) {
    extern __shared__ char smem[];
    const uint32_t sb = smem_u32(smem);
    const int tid  = threadIdx.x;
    const int lane = tid & 31;
    const int wid  = tid >> 5;
    const int warpM = wid & 3;    // 4 warps over M -> 32 rows each
    const int warpN = wid >> 2;   // 2 warps over N -> 64 cols each

    const int m0 = blockIdx.y * BM;
    const int n0 = blockIdx.x * BN;     // blockIdx.x == Jblk

    const char* aG = (const char*)(g_ah + (size_t)m0 * KTOT);
    const uint32_t* wpG = g_wp + (size_t)blockIdx.x * (64 * 8 * 32 * 2);

    // A cp.async mapping: 32 rows x 8 chunks of 16B per pass
    const int lr = tid >> 3;
    const int lc = (tid & 7) * 16;
    const uint32_t ld_sw0 = swz(lr * 128 + lc);

    auto load_stage = [&](int kc, int s) {
        const uint32_t aS = sb + s * STAGE_BYTES;
        const uint32_t pS = aS + A_BYTES;
        const char* ag = aG + (size_t)lr * (KTOT * 2) + kc * (BK * 2) + lc;
        #pragma unroll
        for (int it = 0; it < 4; it++)            // A: 128 rows fp16
            cp_async16(aS + ld_sw0 + it * 4096,
                       ag + (size_t)it * 32 * KTOT * 2);
        // packed B: 8 KB contiguous slab = wpG[kc*4 .. kc*4+3][Jp][lane][e]
        const char* pg = (const char*)(wpG + (size_t)kc * 4 * 512) + tid * 32;
        cp_async16(pS + tid * 32,      pg);
        cp_async16(pS + tid * 32 + 16, pg + 16);
    };

    // hoisted A ldmatrix bases (ki=0)
    uint32_t aBase[2];
    #pragma unroll
    for (int mi = 0; mi < 2; mi++) {
        const int row = warpM * 32 + mi * 16 + (lane & 15);
        const int ko  = (lane >> 4) * 8;
        aBase[mi] = swz(row * 128 + ko * 2);
    }
    // packed-B smem offset: [Ilocal][Jp=warpN*4+nj][lane][2]
    const uint32_t pOff = A_BYTES + (uint32_t)(warpN * 4) * 256 + lane * 8;

    #pragma unroll
    for (int s = 0; s < STAGES - 1; s++) { load_stage(s, s); cp_commit(); }

    float acc[2][8][4] = {};

    for (int kc = 0; kc < NCHUNK; kc++) {
        cp_wait<STAGES - 2>();
        __syncthreads();

        if (kc + STAGES - 1 < NCHUNK)
            load_stage(kc + STAGES - 1, (kc + STAGES - 1) % STAGES);
        cp_commit();

        const uint32_t stS = sb + (kc % STAGES) * STAGE_BYTES;
        const uint32_t pS  = stS + pOff;

        #pragma unroll
        for (int ki = 0; ki < BK / 16; ki++) {
            const uint32_t kOff = ki * 32;        // XOR-safe k step for A
            uint32_t afr[2][4];
            #pragma unroll
            for (int mi = 0; mi < 2; mi++)
                ldsm_x4(afr[mi], stS + (aBase[mi] ^ kOff));

            #pragma unroll
            for (int nj = 0; nj < 4; nj++) {      // n16 tiles
                uint32_t w0, w1;
                lds_v2(w0, w1, pS + ki * 2048 + nj * 256);
                uint32_t b[4];
                b[0] = prmt(w0); b[1] = prmt(w0 >> 16);   // n0-7:  k0-7, k8-15
                b[2] = prmt(w1); b[3] = prmt(w1 >> 16);   // n8-15: k0-7, k8-15
                #pragma unroll
                for (int mi = 0; mi < 2; mi++) {
                    mma16816(acc[mi][nj * 2],     afr[mi], b);
                    mma16816(acc[mi][nj * 2 + 1], afr[mi], b + 2);
                }
            }
        }
    }

    // ---- epilogue: direct coalesced-by-quad float2 stores
    float* cBase = C + (size_t)(m0 + warpM * 32) * NCOLS + n0 + warpN * 64;
    const int cr = lane >> 2;
    const int cc = (lane & 3) * 2;
    #pragma unroll
    for (int mi = 0; mi < 2; mi++) {
        #pragma unroll
        for (int nj = 0; nj < 8; nj++) {
            float* p0 = cBase + (size_t)(mi * 16 + cr) * NCOLS + nj * 8 + cc;
            float* p1 = p0 + 8 * NCOLS;
            *reinterpret_cast<float2*>(p0) = make_float2(acc[mi][nj][0], acc[mi][nj][1]);
            *reinterpret_cast<float2*>(p1) = make_float2(acc[mi][nj][2], acc[mi][nj][3]);
        }
    }
}

// ---------------------------------------------------------------- launch
extern "C" void kernel_launch(void* const* d_in, const int* in_sizes, int n_in,
                              void* d_out, int out_size) {
    (void)in_sizes; (void)n_in; (void)out_size;
    const float* A = (const float*)d_in[0];
    const float* W = (const float*)d_in[1];
    float* C = (float*)d_out;

    prep_kernel<<<CONV_BLOCKS + PACK_BLOCKS, 256>>>(
        reinterpret_cast<const float4*>(A), W);

    cudaFuncSetAttribute(gemm_hmma_kernel,
                         cudaFuncAttributeMaxDynamicSharedMemorySize, SMEM_TOTAL);
    gemm_hmma_kernel<<<dim3(NCOLS / BN, MROWS / BM), TPB, SMEM_TOTAL>>>(C);
}

// round 8
// speedup vs baseline: 1.3711x; 1.0023x over previous
#include <cuda_runtime.h>
#include <cuda_fp16.h>
#include <cstdint>
#include <cstddef>

#define DEVINL __device__ __forceinline__

constexpr int MROWS = 16384;
constexpr int KTOT  = 1024;
constexpr int NCOLS = 1024;

// GEMM tiling: CTA 128x128, warp tile 32x64 (8 warps: 4 over M, 2 over N), 2 CTAs/SM
constexpr int BM = 128, BN = 128, BK = 64;
constexpr int STAGES = 3;
constexpr int TPB = 256;
constexpr int NCHUNK = KTOT / BK;               // 16
constexpr int KI_STEPS = BK / 16;               // 4

constexpr int A_BYTES = BM * BK * 2;            // 16 KB (fp16, SW128)
constexpr int P_BYTES = 8 * 1024;               // 8 KB packed-B selectors
constexpr int STAGE_BYTES = A_BYTES + P_BYTES;  // 24 KB
constexpr int SMEM_TOTAL = STAGES * STAGE_BYTES; // 72 KB (x2 CTAs = 144 KB/SM)

// Static device scratch (allocation-free rule)
__device__ __half g_ah[(size_t)MROWS * KTOT];   // A converted to fp16
// Packed B selectors: [Jblk(8)][I(64)][Jp(8)][lane(32)][e(2)] u32  (1 MB)
// J = n/8 (n8-tile), I = k/16 (k16-tile), Jblk=J>>4, Jp=(J>>1)&7, e=J&1.
// Word w = s0 | (s1<<16); s = 0x0101 | (c_lo<<4) | (c_hi<<12);
// code c = rint(2*clip(x)) + 1  in {0,1,2}  ->  LUT byte {0xB8, 0x00, 0x38}.
__device__ uint32_t g_wp[8 * 64 * 8 * 32 * 2];

constexpr uint32_t PRMT_LUT = 0x003800B8u;      // idx0=-0.5h idx1=0 idx2=+0.5h

// prep split
constexpr int CONV_BLOCKS = 4096;   // A convert: 4 float4 per thread
constexpr int PACK_BLOCKS = 1024;   // 1024 blk * 8 warps = 8192 = 128 J * 64 I
constexpr int CONV_STRIDE = CONV_BLOCKS * 256;

// ---------------------------------------------------------------- helpers
DEVINL uint32_t smem_u32(const void* p) {
    uint32_t r;
    asm("{ .reg .u64 t; cvta.to.shared.u64 t, %1; cvt.u32.u64 %0, t; }"
        : "=r"(r) : "l"(p));
    return r;
}
DEVINL uint32_t swz(uint32_t off) { return off ^ ((off >> 3) & 0x70); }
DEVINL void cp_async16(uint32_t s, const void* g) {
    asm volatile("cp.async.cg.shared.global [%0], [%1], 16;"
                 :: "r"(s), "l"(g) : "memory");
}
DEVINL void cp_commit() { asm volatile("cp.async.commit_group;" ::: "memory"); }
template <int N> DEVINL void cp_wait() {
    asm volatile("cp.async.wait_group %0;" :: "n"(N) : "memory");
}
DEVINL void ldsm_x4(uint32_t* r, uint32_t addr) {
    asm volatile("ldmatrix.sync.aligned.m8n8.x4.shared.b16 {%0,%1,%2,%3}, [%4];"
                 : "=r"(r[0]), "=r"(r[1]), "=r"(r[2]), "=r"(r[3]) : "r"(addr));
}
DEVINL void lds_v2(uint32_t& w0, uint32_t& w1, uint32_t addr) {
    asm volatile("ld.shared.v2.u32 {%0, %1}, [%2];"
                 : "=r"(w0), "=r"(w1) : "r"(addr));
}
DEVINL uint32_t prmt(uint32_t sel) {   // non-volatile: scheduler may place freely
    uint32_t d;
    asm("prmt.b32 %0, %1, 0, %2;" : "=r"(d) : "r"(PRMT_LUT), "r"(sel));
    return d;
}
DEVINL void mma16816(float* c, const uint32_t* a, const uint32_t* b) {
    asm volatile(
        "mma.sync.aligned.m16n8k16.row.col.f32.f16.f16.f32 "
        "{%0,%1,%2,%3}, {%4,%5,%6,%7}, {%8,%9}, {%0,%1,%2,%3};"
        : "+f"(c[0]), "+f"(c[1]), "+f"(c[2]), "+f"(c[3])
        : "r"(a[0]), "r"(a[1]), "r"(a[2]), "r"(a[3]), "r"(b[0]), "r"(b[1]));
}
DEVINL uint32_t pack_half2(float x, float y) {
    __half2 h = __floats2half2_rn(x, y);
    return *reinterpret_cast<uint32_t*>(&h);
}
DEVINL uint32_t wcode(float x) {       // quantize -> selector code {0,1,2}
    x = fminf(fmaxf(x, -0.5f), 0.5f);
    return (uint32_t)(int)(rintf(x * 2.0f) + 1.0f);
}

// -------------------------------------------- merged prep kernel (unchanged)
__global__ void prep_kernel(const float4* __restrict__ a,
                            const float* __restrict__ w) {
    const int bid = blockIdx.x;
    const int t   = threadIdx.x;

    if (bid < CONV_BLOCKS) {           // A fp32 -> fp16, MLP=4
        const size_t base = (size_t)bid * 256 + t;
        float4 v0 = a[base];
        float4 v1 = a[base + CONV_STRIDE];
        float4 v2 = a[base + 2 * (size_t)CONV_STRIDE];
        float4 v3 = a[base + 3 * (size_t)CONV_STRIDE];
        uint2* out = reinterpret_cast<uint2*>(g_ah);
        out[base]                           = make_uint2(pack_half2(v0.x, v0.y), pack_half2(v0.z, v0.w));
        out[base + CONV_STRIDE]             = make_uint2(pack_half2(v1.x, v1.y), pack_half2(v1.z, v1.w));
        out[base + 2 * (size_t)CONV_STRIDE] = make_uint2(pack_half2(v2.x, v2.y), pack_half2(v2.z, v2.w));
        out[base + 3 * (size_t)CONV_STRIDE] = make_uint2(pack_half2(v3.x, v3.y), pack_half2(v3.z, v3.w));
    } else {                           // W quantize + pack selectors
        const int g    = (bid - CONV_BLOCKS) * 8 + (t >> 5);  // 0..8191
        const int lane = t & 31;
        const int J = g >> 6;          // n8-tile 0..127
        const int I = g & 63;          // k16-tile 0..63
        const int n  = J * 8 + (lane >> 2);
        const int kb = I * 16 + (lane & 3) * 2;
        const uint32_t c0 = wcode(w[(size_t)kb * NCOLS + n]);
        const uint32_t c1 = wcode(w[(size_t)(kb + 1) * NCOLS + n]);
        const uint32_t c2 = wcode(w[(size_t)(kb + 8) * NCOLS + n]);
        const uint32_t c3 = wcode(w[(size_t)(kb + 9) * NCOLS + n]);
        const uint32_t s0 = 0x0101u | (c0 << 4) | (c1 << 12);
        const uint32_t s1 = 0x0101u | (c2 << 4) | (c3 << 12);
        const int Jblk = J >> 4, Jp = (J >> 1) & 7, e = J & 1;
        g_wp[(((size_t)(Jblk * 64 + I) * 8 + Jp) * 32 + lane) * 2 + e] = s0 | (s1 << 16);
    }
}

// ------------------------------------------------------------- main GEMM
__global__ void __launch_bounds__(TPB, 2)
gemm_hmma_kernel(float* __restrict__ C) {
    extern __shared__ char smem[];
    const uint32_t sb = smem_u32(smem);
    const int tid  = threadIdx.x;
    const int lane = tid & 31;
    const int wid  = tid >> 5;
    const int warpM = wid & 3;    // 4 warps over M -> 32 rows each
    const int warpN = wid >> 2;   // 2 warps over N -> 64 cols each

    const int m0 = blockIdx.y * BM;
    const int n0 = blockIdx.x * BN;     // blockIdx.x == Jblk

    const char* aG = (const char*)(g_ah + (size_t)m0 * KTOT);
    const uint32_t* wpG = g_wp + (size_t)blockIdx.x * (64 * 8 * 32 * 2);

    // A cp.async mapping: 32 rows x 8 chunks of 16B per pass
    const int lr = tid >> 3;
    const int lc = (tid & 7) * 16;
    const uint32_t ld_sw0 = swz(lr * 128 + lc);

    auto load_stage = [&](int kc, int s) {
        const uint32_t aS = sb + s * STAGE_BYTES;
        const uint32_t pS = aS + A_BYTES;
        const char* ag = aG + (size_t)lr * (KTOT * 2) + kc * (BK * 2) + lc;
        #pragma unroll
        for (int it = 0; it < 4; it++)            // A: 128 rows fp16
            cp_async16(aS + ld_sw0 + it * 4096,
                       ag + (size_t)it * 32 * KTOT * 2);
        const char* pg = (const char*)(wpG + (size_t)kc * 4 * 512) + tid * 32;
        cp_async16(pS + tid * 32,      pg);
        cp_async16(pS + tid * 32 + 16, pg + 16);
    };

    // hoisted A ldmatrix bases (ki=0)
    uint32_t aBase[2];
    #pragma unroll
    for (int mi = 0; mi < 2; mi++) {
        const int row = warpM * 32 + mi * 16 + (lane & 15);
        const int ko  = (lane >> 4) * 8;
        aBase[mi] = swz(row * 128 + ko * 2);
    }
    // packed-B smem offset: [Ilocal][Jp=warpN*4+nj][lane][2]
    const uint32_t pOff = A_BYTES + (uint32_t)(warpN * 4) * 256 + lane * 8;

    #pragma unroll
    for (int s = 0; s < STAGES - 1; s++) { load_stage(s, s); cp_commit(); }

    float acc[2][8][4] = {};
    uint32_t afr[2][2][4];      // ping-pong A fragments
    uint32_t bw[2][4][2];       // ping-pong packed-B words

    for (int kc = 0; kc < NCHUNK; kc++) {
        cp_wait<STAGES - 2>();
        __syncthreads();

        if (kc + STAGES - 1 < NCHUNK)
            load_stage(kc + STAGES - 1, (kc + STAGES - 1) % STAGES);
        cp_commit();

        const uint32_t stS = sb + (kc % STAGES) * STAGE_BYTES;
        const uint32_t pS  = stS + pOff;

        // prime ki=0: loads issued before any MMA of this chunk
        #pragma unroll
        for (int nj = 0; nj < 4; nj++)
            lds_v2(bw[0][nj][0], bw[0][nj][1], pS + nj * 256);
        #pragma unroll
        for (int mi = 0; mi < 2; mi++)
            ldsm_x4(afr[0][mi], stS + aBase[mi]);

        #pragma unroll
        for (int ki = 0; ki < KI_STEPS; ki++) {
            const int cur = ki & 1, nxt = cur ^ 1;

            // software pipeline: ki+1 loads issue BEFORE ki's MMAs (volatile
            // program order guarantees the scheduler sees loads first)
            if (ki < KI_STEPS - 1) {
                const uint32_t pNext = pS + (ki + 1) * 2048;
                #pragma unroll
                for (int nj = 0; nj < 4; nj++)
                    lds_v2(bw[nxt][nj][0], bw[nxt][nj][1], pNext + nj * 256);
                const uint32_t kOff = (ki + 1) * 32;     // XOR-safe k step
                #pragma unroll
                for (int mi = 0; mi < 2; mi++)
                    ldsm_x4(afr[nxt][mi], stS + (aBase[mi] ^ kOff));
            }

            #pragma unroll
            for (int nj = 0; nj < 4; nj++) {
                const uint32_t w0 = bw[cur][nj][0], w1 = bw[cur][nj][1];
                uint32_t b[4];
                b[0] = prmt(w0); b[1] = prmt(w0 >> 16);   // n0-7:  k0-7, k8-15
                b[2] = prmt(w1); b[3] = prmt(w1 >> 16);   // n8-15: k0-7, k8-15
                #pragma unroll
                for (int mi = 0; mi < 2; mi++) {
                    mma16816(acc[mi][nj * 2],     afr[cur][mi], b);
                    mma16816(acc[mi][nj * 2 + 1], afr[cur][mi], b + 2);
                }
            }
        }
    }

    // ---- epilogue: direct coalesced-by-quad float2 stores
    float* cBase = C + (size_t)(m0 + warpM * 32) * NCOLS + n0 + warpN * 64;
    const int cr = lane >> 2;
    const int cc = (lane & 3) * 2;
    #pragma unroll
    for (int mi = 0; mi < 2; mi++) {
        #pragma unroll
        for (int nj = 0; nj < 8; nj++) {
            float* p0 = cBase + (size_t)(mi * 16 + cr) * NCOLS + nj * 8 + cc;
            float* p1 = p0 + 8 * NCOLS;
            *reinterpret_cast<float2*>(p0) = make_float2(acc[mi][nj][0], acc[mi][nj][1]);
            *reinterpret_cast<float2*>(p1) = make_float2(acc[mi][nj][2], acc[mi][nj][3]);
        }
    }
}

// ---------------------------------------------------------------- launch
extern "C" void kernel_launch(void* const* d_in, const int* in_sizes, int n_in,
                              void* d_out, int out_size) {
    (void)in_sizes; (void)n_in; (void)out_size;
    const float* A = (const float*)d_in[0];
    const float* W = (const float*)d_in[1];
    float* C = (float*)d_out;

    prep_kernel<<<CONV_BLOCKS + PACK_BLOCKS, 256>>>(
        reinterpret_cast<const float4*>(A), W);

    cudaFuncSetAttribute(gemm_hmma_kernel,
                         cudaFuncAttributeMaxDynamicSharedMemorySize, SMEM_TOTAL);
    gemm_hmma_kernel<<<dim3(NCOLS / BN, MROWS / BM), TPB, SMEM_TOTAL>>>(C);
}

// round 9
// speedup vs baseline: 1.4607x; 1.0654x over previous
#include <cuda_runtime.h>
#include <cuda_fp16.h>
#include <cstdint>
#include <cstddef>

#define DEVINL __device__ __forceinline__

constexpr int MROWS = 16384;
constexpr int KTOT  = 1024;
constexpr int NCOLS = 1024;

// GEMM tiling: CTA 128x128, warp tile 32x64 (8 warps: 4 over M, 2 over N), 2 CTAs/SM
constexpr int BM = 128, BN = 128, BK = 64;      // BK in fp16 elements (128B row)
constexpr int STAGES = 3;
constexpr int TPB = 256;
constexpr int NCHUNK = KTOT / BK;               // 16

constexpr int A_BYTES = BM * BK * 2;            // 16 KB
constexpr int B_BYTES = BN * BK * 2;            // 16 KB
constexpr int STAGE_BYTES = A_BYTES + B_BYTES;  // 32 KB
constexpr int SMEM_TOTAL = STAGES * STAGE_BYTES; // 96 KB (x2 CTAs = 192 KB/SM)

// Static device scratch (allocation-free rule)
__device__ __half g_ah[(size_t)MROWS * KTOT];   // A converted to fp16
__device__ __half g_wt[(size_t)NCOLS * KTOT];   // W quantized, [n][k] K-major

// prep split: conv does 8 independent float4 per thread (MLP=8)
constexpr int CONV_BLOCKS  = 2048;   // 2048 blk * 256 thr * 8 float4 = 4.19M float4
constexpr int QUANT_BLOCKS = (NCOLS / 32) * (KTOT / 32);  // 1024
constexpr int CONV_STRIDE  = CONV_BLOCKS * 256;           // float4 elements

// ---------------------------------------------------------------- helpers
DEVINL uint32_t smem_u32(const void* p) {
    uint32_t r;
    asm("{ .reg .u64 t; cvta.to.shared.u64 t, %1; cvt.u32.u64 %0, t; }"
        : "=r"(r) : "l"(p));
    return r;
}
DEVINL uint32_t swz(uint32_t off) {            // SW128: bits[6:4] ^= bits[9:7]
    return off ^ ((off >> 3) & 0x70);
}
DEVINL void cp_async16(uint32_t s, const void* g) {
    asm volatile("cp.async.cg.shared.global [%0], [%1], 16;"
                 :: "r"(s), "l"(g) : "memory");
}
DEVINL void cp_commit() {
    asm volatile("cp.async.commit_group;" ::: "memory");
}
template <int N> DEVINL void cp_wait() {
    asm volatile("cp.async.wait_group %0;" :: "n"(N) : "memory");
}
DEVINL void ldsm_x4(uint32_t* r, uint32_t addr) {
    asm volatile("ldmatrix.sync.aligned.m8n8.x4.shared.b16 {%0,%1,%2,%3}, [%4];"
                 : "=r"(r[0]), "=r"(r[1]), "=r"(r[2]), "=r"(r[3]) : "r"(addr));
}
DEVINL void mma16816(float* c, const uint32_t* a, const uint32_t* b) {
    asm volatile(
        "mma.sync.aligned.m16n8k16.row.col.f32.f16.f16.f32 "
        "{%0,%1,%2,%3}, {%4,%5,%6,%7}, {%8,%9}, {%0,%1,%2,%3};"
        : "+f"(c[0]), "+f"(c[1]), "+f"(c[2]), "+f"(c[3])
        : "r"(a[0]), "r"(a[1]), "r"(a[2]), "r"(a[3]), "r"(b[0]), "r"(b[1]));
}
DEVINL uint32_t pack_half2(float x, float y) {
    __half2 h = __floats2half2_rn(x, y);
    return *reinterpret_cast<uint32_t*>(&h);
}

// -------------------------------------------- merged prep kernel
// blocks [0, CONV_BLOCKS):             A fp32 -> fp16 (8 float4/thread, MLP=8)
// blocks [CONV_BLOCKS, +QUANT_BLOCKS): W quantize + transpose
__global__ void prep_kernel(const float4* __restrict__ a,
                            const float* __restrict__ w) {
    const int bid = blockIdx.x;
    const int t   = threadIdx.x;

    if (bid < CONV_BLOCKS) {
        const size_t base = (size_t)bid * 256 + t;
        float4 v[8];
        #pragma unroll
        for (int i = 0; i < 8; i++)                    // 8 independent loads
            v[i] = a[base + (size_t)i * CONV_STRIDE];
        uint2* out = reinterpret_cast<uint2*>(g_ah);
        #pragma unroll
        for (int i = 0; i < 8; i++)
            out[base + (size_t)i * CONV_STRIDE] =
                make_uint2(pack_half2(v[i].x, v[i].y), pack_half2(v[i].z, v[i].w));
    } else {
        __shared__ __half tile[32][33];
        const int tb = bid - CONV_BLOCKS;
        const int n0 = (tb & 31) * 32;
        const int k0 = (tb >> 5) * 32;
        const int tx = t & 31;
        const int ty = t >> 5;
        #pragma unroll
        for (int i = ty; i < 32; i += 8) {
            float x = w[(size_t)(k0 + i) * NCOLS + n0 + tx];
            x = fminf(fmaxf(x, -0.5f), 0.5f);     // clip [-1+delta, 1-delta]
            float y = rintf(x * 2.0f) * 0.5f;     // round-half-even, step 0.5
            tile[i][tx] = __float2half_rn(y);     // exact in fp16
        }
        __syncthreads();
        #pragma unroll
        for (int i = ty; i < 32; i += 8) {
            g_wt[(size_t)(n0 + i) * KTOT + k0 + tx] = tile[tx][i];
        }
    }
}

// ------------------------------------------------------------- main GEMM
// (exact R4 kernel — proven 83.7 us, tensor 67.2%)
__global__ void __launch_bounds__(TPB, 2)
gemm_hmma_kernel(float* __restrict__ C) {
    extern __shared__ char smem[];
    const uint32_t sb = smem_u32(smem);
    const int tid  = threadIdx.x;
    const int lane = tid & 31;
    const int wid  = tid >> 5;
    const int warpM = wid & 3;    // 4 warps over M -> 32 rows each
    const int warpN = wid >> 2;   // 2 warps over N -> 64 cols each

    const int m0 = blockIdx.y * BM;
    const int n0 = blockIdx.x * BN;

    const char* aG = (const char*)(g_ah + (size_t)m0 * KTOT);
    const char* bG = (const char*)(g_wt + (size_t)n0 * KTOT);

    // per-thread cp.async mapping: 32 rows x 8 chunks of 16B per pass
    const int lr = tid >> 3;             // row 0..31
    const int lc = (tid & 7) * 16;       // byte offset within 128B row
    const uint32_t ld_sw0 = swz(lr * 128 + lc);   // same XOR mask all passes

    auto load_stage = [&](int kc, int s) {
        const uint32_t aS = sb + s * STAGE_BYTES;
        const uint32_t bS = aS + A_BYTES;
        const char* ag = aG + (size_t)lr * (KTOT * 2) + kc * (BK * 2) + lc;
        const char* bg = bG + (size_t)lr * (KTOT * 2) + kc * (BK * 2) + lc;
        #pragma unroll
        for (int it = 0; it < 4; it++) {
            const uint32_t sw = ld_sw0 + it * 32 * 128;
            cp_async16(aS + sw, ag + (size_t)it * 32 * KTOT * 2);
            cp_async16(bS + sw, bg + (size_t)it * 32 * KTOT * 2);
        }
    };

    // hoisted ldmatrix address bases (offset within stage, ki=0)
    uint32_t aBase[2], bBase[4];
    #pragma unroll
    for (int mi = 0; mi < 2; mi++) {
        const int row = warpM * 32 + mi * 16 + (lane & 15);
        const int ko  = (lane >> 4) * 8;
        aBase[mi] = swz(row * 128 + ko * 2);
    }
    #pragma unroll
    for (int nj = 0; nj < 4; nj++) {
        const int row = warpN * 64 + nj * 16 + ((lane >> 4) << 3) + (lane & 7);
        const int ko  = ((lane >> 3) & 1) * 8;
        bBase[nj] = swz(row * 128 + ko * 2) + A_BYTES;
    }

    // prologue: stages 0..STAGES-2
    #pragma unroll
    for (int s = 0; s < STAGES - 1; s++) {
        load_stage(s, s);
        cp_commit();
    }

    float acc[2][8][4] = {};

    for (int kc = 0; kc < NCHUNK; kc++) {
        cp_wait<STAGES - 2>();
        __syncthreads();   // stage kc ready for all; prev compute finished

        // prefetch stage kc+STAGES-1 into the slot just freed
        if (kc + STAGES - 1 < NCHUNK)
            load_stage(kc + STAGES - 1, (kc + STAGES - 1) % STAGES);
        cp_commit();       // empty groups keep group counts uniform

        const uint32_t stS = sb + (kc % STAGES) * STAGE_BYTES;

        #pragma unroll
        for (int ki = 0; ki < BK / 16; ki++) {           // 4 k16 steps
            const uint32_t kOff = ki * 32;               // 16 fp16 = 32 B; XOR-safe
            uint32_t afr[2][4], bfr[4][4];
            #pragma unroll
            for (int mi = 0; mi < 2; mi++)
                ldsm_x4(afr[mi], stS + (aBase[mi] ^ kOff));
            #pragma unroll
            for (int nj = 0; nj < 4; nj++)
                ldsm_x4(bfr[nj], stS + (bBase[nj] ^ kOff));
            #pragma unroll
            for (int mi = 0; mi < 2; mi++)
                #pragma unroll
                for (int nj = 0; nj < 8; nj++)
                    mma16816(acc[mi][nj], afr[mi], &bfr[nj >> 1][(nj & 1) * 2]);
        }
    }

    // ---- epilogue: direct coalesced-by-quad float2 stores
    float* cBase = C + (size_t)(m0 + warpM * 32) * NCOLS + n0 + warpN * 64;
    const int cr = lane >> 2;
    const int cc = (lane & 3) * 2;
    #pragma unroll
    for (int mi = 0; mi < 2; mi++) {
        #pragma unroll
        for (int nj = 0; nj < 8; nj++) {
            float* p0 = cBase + (size_t)(mi * 16 + cr) * NCOLS + nj * 8 + cc;
            float* p1 = p0 + 8 * NCOLS;
            *reinterpret_cast<float2*>(p0) = make_float2(acc[mi][nj][0], acc[mi][nj][1]);
            *reinterpret_cast<float2*>(p1) = make_float2(acc[mi][nj][2], acc[mi][nj][3]);
        }
    }
}

// ---------------------------------------------------------------- launch
extern "C" void kernel_launch(void* const* d_in, const int* in_sizes, int n_in,
                              void* d_out, int out_size) {
    (void)in_sizes; (void)n_in; (void)out_size;
    const float* A = (const float*)d_in[0];   // [16384, 1024] fp32
    const float* W = (const float*)d_in[1];   // [1024, 1024] fp32
    float* C = (float*)d_out;                 // [16384, 1024] fp32

    prep_kernel<<<CONV_BLOCKS + QUANT_BLOCKS, 256>>>(
        reinterpret_cast<const float4*>(A), W);

    cudaFuncSetAttribute(gemm_hmma_kernel,
                         cudaFuncAttributeMaxDynamicSharedMemorySize, SMEM_TOTAL);
    gemm_hmma_kernel<<<dim3(NCOLS / BN, MROWS / BM), TPB, SMEM_TOTAL>>>(C);
}